// round 6
// baseline (speedup 1.0000x reference)
#include <cuda_runtime.h>
#include <cuda_bf16.h>

// GradeWiseLinear: block-diagonal 16x16 linear (blocks 1,4,6,4,1) + bias.
// 2,097,152 rows x 16 fp32 (8.4M float4s). HBM streaming, 268 MB traffic.
//
// R4: lane-per-float4 layout. Every LDG.128/STG.128 is fully coalesced
// (512B contiguous per instruction, 128B per L1 wavefront) instead of the
// previous 64B-strided row-per-thread pattern (32B per wavefront). Grade
// blocks crossing float4 boundaries are handled with 6 warp shuffles and a
// role-uniform dense 10-wide dot product per output, using a zero-padded
// per-role weight table (built once per block in smem, kept in registers).

#define TPB 256
#define RPT 2   // float4s per thread

#define FULLMASK 0xffffffffu

__global__ void __launch_bounds__(TPB, 3)
gradewise_linear_kernel(const float* __restrict__ x,
                        const float* __restrict__ w0, const float* __restrict__ b0,
                        const float* __restrict__ w1, const float* __restrict__ b1,
                        const float* __restrict__ w2, const float* __restrict__ b2,
                        const float* __restrict__ w3, const float* __restrict__ b3,
                        const float* __restrict__ w4, const float* __restrict__ b4,
                        float* __restrict__ out, int n_f4)
{
    // Padded dense weight table: for output o = 4k+j, window over
    // rel = i - 4k + 3 in [0,10) (zero where no block entry).
    // swf[o*12 + m], biases sbf[o].
    __shared__ __align__(16) float swf[16 * 12];
    __shared__ float sbf[16];

    {
        int t = threadIdx.x;
        if (t < 16) {
            int o = t;
#pragma unroll
            for (int m = 0; m < 12; m++) swf[o * 12 + m] = 0.0f;

            int lo, d;
            const float* wg;
            const float* bg;
            if (o < 1)       { lo = 0;  d = 1; wg = w0; bg = b0; }
            else if (o < 5)  { lo = 1;  d = 4; wg = w1; bg = b1; }
            else if (o < 11) { lo = 5;  d = 6; wg = w2; bg = b2; }
            else if (o < 15) { lo = 11; d = 4; wg = w3; bg = b3; }
            else             { lo = 15; d = 1; wg = w4; bg = b4; }

            int a = o - lo;              // row within grade block
            int base4 = o & ~3;          // 4k
            for (int bcol = 0; bcol < d; bcol++) {
                int i = lo + bcol;       // global input index
                int m = i - base4 + 3;   // 0..9 by construction
                swf[o * 12 + m] = wg[a * d + bcol];
            }
            sbf[o] = bg[a];
        }
    }
    __syncthreads();

    // Per-lane role: which float4 of its row this lane owns.
    const int k = threadIdx.x & 3;

    // Load this role's 4x10 weights + 4 biases into registers (broadcast LDS).
    float W[40], B[4];
#pragma unroll
    for (int j = 0; j < 4; j++) {
#pragma unroll
        for (int m = 0; m < 10; m++)
            W[j * 10 + m] = swf[(4 * k + j) * 12 + m];
        B[j] = sbf[4 * k + j];
    }

    const float4* x4 = reinterpret_cast<const float4*>(x);
    float4* o4 = reinterpret_cast<float4*>(out);

    int base = blockIdx.x * (TPB * RPT) + threadIdx.x;

#pragma unroll
    for (int t = 0; t < RPT; t++) {
        int idx = base + t * TPB;
        if (idx >= n_f4) break;

        float4 v = __ldcs(x4 + idx);

        // Neighbor exchange: rel window [-3..7) around own base.
        // up (lane-1) supplies rel -3,-2,-1 = its .y,.z,.w
        // dn (lane+1) supplies rel 4,5,6    = its .x,.y,.z
        // Cross-row leakage at role boundaries is multiplied by zero weights.
        float um3 = __shfl_up_sync(FULLMASK, v.y, 1);
        float um2 = __shfl_up_sync(FULLMASK, v.z, 1);
        float um1 = __shfl_up_sync(FULLMASK, v.w, 1);
        float dp4 = __shfl_down_sync(FULLMASK, v.x, 1);
        float dp5 = __shfl_down_sync(FULLMASK, v.y, 1);
        float dp6 = __shfl_down_sync(FULLMASK, v.z, 1);

        float loc0 = um3, loc1 = um2, loc2 = um1;
        float loc3 = v.x, loc4 = v.y, loc5 = v.z, loc6 = v.w;
        float loc7 = dp4, loc8 = dp5, loc9 = dp6;

        float r[4];
#pragma unroll
        for (int j = 0; j < 4; j++) {
            float acc = B[j];
            acc = fmaf(W[j * 10 + 0], loc0, acc);
            acc = fmaf(W[j * 10 + 1], loc1, acc);
            acc = fmaf(W[j * 10 + 2], loc2, acc);
            acc = fmaf(W[j * 10 + 3], loc3, acc);
            acc = fmaf(W[j * 10 + 4], loc4, acc);
            acc = fmaf(W[j * 10 + 5], loc5, acc);
            acc = fmaf(W[j * 10 + 6], loc6, acc);
            acc = fmaf(W[j * 10 + 7], loc7, acc);
            acc = fmaf(W[j * 10 + 8], loc8, acc);
            acc = fmaf(W[j * 10 + 9], loc9, acc);
            r[j] = acc;
        }

        __stcs(o4 + idx, make_float4(r[0], r[1], r[2], r[3]));
    }
}

extern "C" void kernel_launch(void* const* d_in, const int* in_sizes, int n_in,
                              void* d_out, int out_size)
{
    const float* x  = (const float*)d_in[0];
    const float* w0 = (const float*)d_in[1];
    const float* b0 = (const float*)d_in[2];
    const float* w1 = (const float*)d_in[3];
    const float* b1 = (const float*)d_in[4];
    const float* w2 = (const float*)d_in[5];
    const float* b2 = (const float*)d_in[6];
    const float* w3 = (const float*)d_in[7];
    const float* b3 = (const float*)d_in[8];
    const float* w4 = (const float*)d_in[9];
    const float* b4 = (const float*)d_in[10];
    float* out = (float*)d_out;

    int n_f4 = in_sizes[0] / 4;               // total float4s
    int per_block = TPB * RPT;
    int blocks = (n_f4 + per_block - 1) / per_block;

    gradewise_linear_kernel<<<blocks, TPB>>>(
        x, w0, b0, w1, b1, w2, b2, w3, b3, w4, b4, out, n_f4);
}

// round 7
// speedup vs baseline: 1.1382x; 1.1382x over previous
#include <cuda_runtime.h>
#include <cuda_bf16.h>

// GradeWiseLinear: block-diagonal 16x16 linear (blocks 1,4,6,4,1) + bias.
// 2,097,152 rows x 16 fp32. HBM streaming, 268 MB total traffic.
//
// R7: fully-coalesced LDG/STG via warp-local shared-memory transpose.
//  - warp tile = 32 rows (2 KB): 4 coalesced LDG.128 -> padded smem ->
//    each lane reads ITS row (conflict-free LDS.128, PAD=20 words) ->
//    R3 compute with smem weight broadcasts -> padded smem -> 4 coalesced
//    STG.128. No shuffles; 2 __syncwarp per tile; next-tile loads prefetched
//    before compute.

#define TPB 256
#define NWARP 8
#define PAD 20              // words per staged row (80B, 16B-aligned, conflict-free)
#define TILE_WORDS (32 * PAD)

// weight smem layout (same as R3):
//  [0..15]  W1 (4x4) as s4[0..3]; [16..19] B1
//  [20..67] W2 padded 6x8 as s4[5+2oo],s4[6+2oo]; [68..75] B2
//  [76..91] W3 as s4[19+oo]; [92..95] B3
//  [96..99] (w0,b0,w4,b4) as s4[24]
#define S_TOT 104

__global__ void __launch_bounds__(TPB, 3)
gradewise_linear_kernel(const float* __restrict__ x,
                        const float* __restrict__ w0, const float* __restrict__ b0,
                        const float* __restrict__ w1, const float* __restrict__ b1,
                        const float* __restrict__ w2, const float* __restrict__ b2,
                        const float* __restrict__ w3, const float* __restrict__ b3,
                        const float* __restrict__ w4, const float* __restrict__ b4,
                        float* __restrict__ out, int n_f4, int n_tiles)
{
    __shared__ __align__(16) float s[S_TOT];
    __shared__ __align__(16) float stage[NWARP][2][TILE_WORDS];

    {
        int t = threadIdx.x;
        if (t < S_TOT) {
            float v = 0.0f;
            if      (t < 16) v = w1[t];
            else if (t < 20) v = b1[t - 16];
            else if (t < 68) { int rr = (t - 20) >> 3, cc = (t - 20) & 7;
                               if (cc < 6) v = w2[rr * 6 + cc]; }
            else if (t < 76) { int cc = t - 68; if (cc < 6) v = b2[cc]; }
            else if (t < 92) v = w3[t - 76];
            else if (t < 96) v = b3[t - 92];
            else if (t == 96) v = w0[0];
            else if (t == 97) v = b0[0];
            else if (t == 98) v = w4[0];
            else if (t == 99) v = b4[0];
            s[t] = v;
        }
    }
    __syncthreads();
    const float4* s4 = reinterpret_cast<const float4*>(s);

    const int warp = threadIdx.x >> 5;
    const int lane = threadIdx.x & 31;
    float* inb  = &stage[warp][0][0];
    float* outb = &stage[warp][1][0];

    const float4* x4 = reinterpret_cast<const float4*>(x);
    float4* o4 = reinterpret_cast<float4*>(out);

    const int tstride = gridDim.x * NWARP;
    int tile = blockIdx.x * NWARP + warp;

    // prefetch first tile (coalesced, guarded)
    float4 ld0, ld1, ld2, ld3;
    if (tile < n_tiles) {
        int b = tile * 128 + lane;
        ld0 = (b       < n_f4) ? __ldcs(x4 + b)       : make_float4(0,0,0,0);
        ld1 = (b + 32  < n_f4) ? __ldcs(x4 + b + 32)  : make_float4(0,0,0,0);
        ld2 = (b + 64  < n_f4) ? __ldcs(x4 + b + 64)  : make_float4(0,0,0,0);
        ld3 = (b + 96  < n_f4) ? __ldcs(x4 + b + 96)  : make_float4(0,0,0,0);
    }

    while (tile < n_tiles) {
        int next = tile + tstride;

        // ---- stage in: f4 linear idx j*32+lane -> row r=(idx>>2), quad f=(idx&3)
        {
            int r0 = lane >> 2, f0 = lane & 3;   // j=0
            *reinterpret_cast<float4*>(inb + (0 * 8 + r0) * PAD + f0 * 4) = ld0;
            *reinterpret_cast<float4*>(inb + (1 * 8 + r0) * PAD + f0 * 4) = ld1;
            *reinterpret_cast<float4*>(inb + (2 * 8 + r0) * PAD + f0 * 4) = ld2;
            *reinterpret_cast<float4*>(inb + (3 * 8 + r0) * PAD + f0 * 4) = ld3;
        }
        __syncwarp();

        // ---- row read: lane owns row `lane` of this tile (conflict-free)
        float4 v0 = *reinterpret_cast<const float4*>(inb + lane * PAD + 0);
        float4 v1 = *reinterpret_cast<const float4*>(inb + lane * PAD + 4);
        float4 v2 = *reinterpret_cast<const float4*>(inb + lane * PAD + 8);
        float4 v3 = *reinterpret_cast<const float4*>(inb + lane * PAD + 12);

        // ---- prefetch next tile while computing
        if (next < n_tiles) {
            int b = next * 128 + lane;
            ld0 = (b       < n_f4) ? __ldcs(x4 + b)       : make_float4(0,0,0,0);
            ld1 = (b + 32  < n_f4) ? __ldcs(x4 + b + 32)  : make_float4(0,0,0,0);
            ld2 = (b + 64  < n_f4) ? __ldcs(x4 + b + 64)  : make_float4(0,0,0,0);
            ld3 = (b + 96  < n_f4) ? __ldcs(x4 + b + 96)  : make_float4(0,0,0,0);
        }

        // ---- compute (identical math to R3)
        float o[16];
        {
            float4 m = s4[24];
            o[0]  = fmaf(m.x, v0.x, m.y);
            o[15] = fmaf(m.z, v3.w, m.w);
        }
#pragma unroll
        for (int oo = 0; oo < 4; oo++) {
            float4 w = s4[oo];
            float acc = s[16 + oo];
            acc = fmaf(w.x, v0.y, acc);
            acc = fmaf(w.y, v0.z, acc);
            acc = fmaf(w.z, v0.w, acc);
            acc = fmaf(w.w, v1.x, acc);
            o[1 + oo] = acc;
        }
#pragma unroll
        for (int oo = 0; oo < 6; oo++) {
            float4 wa = s4[5 + 2 * oo];
            float4 wb = s4[6 + 2 * oo];
            float acc = s[68 + oo];
            acc = fmaf(wa.x, v1.y, acc);
            acc = fmaf(wa.y, v1.z, acc);
            acc = fmaf(wa.z, v1.w, acc);
            acc = fmaf(wa.w, v2.x, acc);
            acc = fmaf(wb.x, v2.y, acc);
            acc = fmaf(wb.y, v2.z, acc);
            o[5 + oo] = acc;
        }
#pragma unroll
        for (int oo = 0; oo < 4; oo++) {
            float4 w = s4[19 + oo];
            float acc = s[92 + oo];
            acc = fmaf(w.x, v2.w, acc);
            acc = fmaf(w.y, v3.x, acc);
            acc = fmaf(w.z, v3.y, acc);
            acc = fmaf(w.w, v3.z, acc);
            o[11 + oo] = acc;
        }

        // ---- stage out (row layout, conflict-free)
        *reinterpret_cast<float4*>(outb + lane * PAD + 0)  = make_float4(o[0],  o[1],  o[2],  o[3]);
        *reinterpret_cast<float4*>(outb + lane * PAD + 4)  = make_float4(o[4],  o[5],  o[6],  o[7]);
        *reinterpret_cast<float4*>(outb + lane * PAD + 8)  = make_float4(o[8],  o[9],  o[10], o[11]);
        *reinterpret_cast<float4*>(outb + lane * PAD + 12) = make_float4(o[12], o[13], o[14], o[15]);
        __syncwarp();

        // ---- coalesced store: f4 idx j*32+lane from outb
        {
            int r0 = lane >> 2, f0 = lane & 3;
            int b = tile * 128 + lane;
            float4 t0 = *reinterpret_cast<const float4*>(outb + (0 * 8 + r0) * PAD + f0 * 4);
            float4 t1 = *reinterpret_cast<const float4*>(outb + (1 * 8 + r0) * PAD + f0 * 4);
            float4 t2 = *reinterpret_cast<const float4*>(outb + (2 * 8 + r0) * PAD + f0 * 4);
            float4 t3 = *reinterpret_cast<const float4*>(outb + (3 * 8 + r0) * PAD + f0 * 4);
            if (b      < n_f4) __stcs(o4 + b,      t0);
            if (b + 32 < n_f4) __stcs(o4 + b + 32, t1);
            if (b + 64 < n_f4) __stcs(o4 + b + 64, t2);
            if (b + 96 < n_f4) __stcs(o4 + b + 96, t3);
        }

        tile = next;
    }
}

extern "C" void kernel_launch(void* const* d_in, const int* in_sizes, int n_in,
                              void* d_out, int out_size)
{
    const float* x  = (const float*)d_in[0];
    const float* w0 = (const float*)d_in[1];
    const float* b0 = (const float*)d_in[2];
    const float* w1 = (const float*)d_in[3];
    const float* b1 = (const float*)d_in[4];
    const float* w2 = (const float*)d_in[5];
    const float* b2 = (const float*)d_in[6];
    const float* w3 = (const float*)d_in[7];
    const float* b3 = (const float*)d_in[8];
    const float* w4 = (const float*)d_in[9];
    const float* b4 = (const float*)d_in[10];
    float* out = (float*)d_out;

    int n_f4 = in_sizes[0] / 4;                  // total float4s
    int n_tiles = (n_f4 + 127) / 128;            // 32-row warp tiles

    // persistent grid: ~3 CTAs per SM on 152-SM GB300
    int blocks = 456;
    int max_blocks = (n_tiles + NWARP - 1) / NWARP;
    if (blocks > max_blocks) blocks = max_blocks;

    gradewise_linear_kernel<<<blocks, TPB>>>(
        x, w0, b0, w1, b1, w2, b2, w3, b3, w4, b4, out, n_f4, n_tiles);
}

// round 8
// speedup vs baseline: 1.6479x; 1.4477x over previous
#include <cuda_runtime.h>
#include <cuda_bf16.h>

// GradeWiseLinear: block-diagonal 16x16 linear (blocks 1,4,6,4,1) + bias.
// 2,097,152 rows x 16 fp32 (8,388,608 float4s). 268 MB HBM traffic.
//
// R8: lane-per-float4 (fully coalesced LDG.128/STG.128, 1 wavefront per
// 128B line) + BATCHED loads: each thread issues ITERS=4 independent
// coalesced loads before any shuffle/compute, restoring MLP=4 (R4's
// failure was MLP collapse, not the shuffles). Role-uniform zero-padded
// 10-wide dot product per output; cross-row shuffle leakage is multiplied
// by zero weights (correctness proven in R4, rel_err 6.3e-8).

#define TPB 256
#define ITERS 4
#define FULLMASK 0xffffffffu

__global__ void __launch_bounds__(TPB, 3)
gradewise_linear_kernel(const float* __restrict__ x,
                        const float* __restrict__ w0, const float* __restrict__ b0,
                        const float* __restrict__ w1, const float* __restrict__ b1,
                        const float* __restrict__ w2, const float* __restrict__ b2,
                        const float* __restrict__ w3, const float* __restrict__ b3,
                        const float* __restrict__ w4, const float* __restrict__ b4,
                        float* __restrict__ out, int n_f4)
{
    // Zero-padded dense weight table: output o = 4k+j uses input window
    // rel m = i - 4k + 3 in [0,10); entries outside the grade block are 0.
    __shared__ __align__(16) float swf[16 * 12];
    __shared__ float sbf[16];
    {
        int t = threadIdx.x;
        if (t < 16) {
            int o = t;
#pragma unroll
            for (int m = 0; m < 12; m++) swf[o * 12 + m] = 0.0f;
            int lo, d;
            const float *wg, *bg;
            if (o < 1)       { lo = 0;  d = 1; wg = w0; bg = b0; }
            else if (o < 5)  { lo = 1;  d = 4; wg = w1; bg = b1; }
            else if (o < 11) { lo = 5;  d = 6; wg = w2; bg = b2; }
            else if (o < 15) { lo = 11; d = 4; wg = w3; bg = b3; }
            else             { lo = 15; d = 1; wg = w4; bg = b4; }
            int a = o - lo;
            int base4 = o & ~3;
            for (int c = 0; c < d; c++)
                swf[o * 12 + (lo + c - base4 + 3)] = wg[a * d + c];
            sbf[o] = bg[a];
        }
    }
    __syncthreads();

    // Lane role: float4 index within its row. Consecutive lanes hold
    // consecutive float4s and iterations stride by 32, so role = lane&3.
    const int k = threadIdx.x & 3;

    float W[40], B[4];
#pragma unroll
    for (int j = 0; j < 4; j++) {
#pragma unroll
        for (int m = 0; m < 10; m++)
            W[j * 10 + m] = swf[(4 * k + j) * 12 + m];
        B[j] = sbf[4 * k + j];
    }

    const float4* x4 = reinterpret_cast<const float4*>(x);
    float4* o4 = reinterpret_cast<float4*>(out);

    const int base = blockIdx.x * (TPB * ITERS) + threadIdx.x;

    // ---- phase 1: issue all ITERS coalesced loads (independent, MLP=4) ----
    float4 v[ITERS];
    int idx[ITERS];
    bool ok[ITERS];
#pragma unroll
    for (int t = 0; t < ITERS; t++) {
        idx[t] = base + t * TPB;
        ok[t] = idx[t] < n_f4;
        v[t] = ok[t] ? __ldcs(x4 + idx[t]) : make_float4(0.f, 0.f, 0.f, 0.f);
    }

    // ---- phase 2: shuffle + compute + store per sub-iteration ----
#pragma unroll
    for (int t = 0; t < ITERS; t++) {
        // rel window [-3..7): up-neighbor supplies rel -3..-1, down rel 4..6.
        float um3 = __shfl_up_sync(FULLMASK, v[t].y, 1);
        float um2 = __shfl_up_sync(FULLMASK, v[t].z, 1);
        float um1 = __shfl_up_sync(FULLMASK, v[t].w, 1);
        float dp4 = __shfl_down_sync(FULLMASK, v[t].x, 1);
        float dp5 = __shfl_down_sync(FULLMASK, v[t].y, 1);
        float dp6 = __shfl_down_sync(FULLMASK, v[t].z, 1);

        float l0 = um3, l1 = um2, l2 = um1;
        float l3 = v[t].x, l4 = v[t].y, l5 = v[t].z, l6 = v[t].w;
        float l7 = dp4, l8 = dp5, l9 = dp6;

        float r[4];
#pragma unroll
        for (int j = 0; j < 4; j++) {
            float acc = B[j];
            acc = fmaf(W[j * 10 + 0], l0, acc);
            acc = fmaf(W[j * 10 + 1], l1, acc);
            acc = fmaf(W[j * 10 + 2], l2, acc);
            acc = fmaf(W[j * 10 + 3], l3, acc);
            acc = fmaf(W[j * 10 + 4], l4, acc);
            acc = fmaf(W[j * 10 + 5], l5, acc);
            acc = fmaf(W[j * 10 + 6], l6, acc);
            acc = fmaf(W[j * 10 + 7], l7, acc);
            acc = fmaf(W[j * 10 + 8], l8, acc);
            acc = fmaf(W[j * 10 + 9], l9, acc);
            r[j] = acc;
        }

        if (ok[t]) __stcs(o4 + idx[t], make_float4(r[0], r[1], r[2], r[3]));
    }
}

extern "C" void kernel_launch(void* const* d_in, const int* in_sizes, int n_in,
                              void* d_out, int out_size)
{
    const float* x  = (const float*)d_in[0];
    const float* w0 = (const float*)d_in[1];
    const float* b0 = (const float*)d_in[2];
    const float* w1 = (const float*)d_in[3];
    const float* b1 = (const float*)d_in[4];
    const float* w2 = (const float*)d_in[5];
    const float* b2 = (const float*)d_in[6];
    const float* w3 = (const float*)d_in[7];
    const float* b3 = (const float*)d_in[8];
    const float* w4 = (const float*)d_in[9];
    const float* b4 = (const float*)d_in[10];
    float* out = (float*)d_out;

    int n_f4 = in_sizes[0] / 4;
    int per_block = TPB * ITERS;
    int blocks = (n_f4 + per_block - 1) / per_block;

    gradewise_linear_kernel<<<blocks, TPB>>>(
        x, w0, b0, w1, b1, w2, b2, w3, b3, w4, b4, out, n_f4);
}

// round 9
// speedup vs baseline: 1.6564x; 1.0052x over previous
#include <cuda_runtime.h>
#include <cuda_bf16.h>

// GradeWiseLinear: block-diagonal 16x16 linear (blocks 1,4,6,4,1) + bias.
// 2,097,152 rows x 16 fp32 (8,388,608 float4s). 268 MB HBM traffic.
//
// R9: R8 structure (lane-per-float4, fully coalesced LDG.128/STG.128,
// role-uniform zero-padded 10-wide dot product, neighbor shuffles) with
// ITERS=8: all 8 independent loads issued before any compute -> ~14.5 MB
// in flight chip-wide (vs 8.5 MB at ITERS=4), targeting the DRAM
// concurrency ceiling. Biases read from smem per use to keep regs <= 85
// (3 CTAs/SM). Block-uniform fast path drops all bounds checks.

#define TPB 256
#define ITERS 8
#define FULLMASK 0xffffffffu

__global__ void __launch_bounds__(TPB, 3)
gradewise_linear_kernel(const float* __restrict__ x,
                        const float* __restrict__ w0, const float* __restrict__ b0,
                        const float* __restrict__ w1, const float* __restrict__ b1,
                        const float* __restrict__ w2, const float* __restrict__ b2,
                        const float* __restrict__ w3, const float* __restrict__ b3,
                        const float* __restrict__ w4, const float* __restrict__ b4,
                        float* __restrict__ out, int n_f4)
{
    // Zero-padded dense weight table: output o = 4k+j uses input window
    // rel m = i - 4k + 3 in [0,10); entries outside the grade block are 0.
    __shared__ __align__(16) float swf[16 * 12];
    __shared__ float sbf[16];
    {
        int t = threadIdx.x;
        if (t < 16) {
            int o = t;
#pragma unroll
            for (int m = 0; m < 12; m++) swf[o * 12 + m] = 0.0f;
            int lo, d;
            const float *wg, *bg;
            if (o < 1)       { lo = 0;  d = 1; wg = w0; bg = b0; }
            else if (o < 5)  { lo = 1;  d = 4; wg = w1; bg = b1; }
            else if (o < 11) { lo = 5;  d = 6; wg = w2; bg = b2; }
            else if (o < 15) { lo = 11; d = 4; wg = w3; bg = b3; }
            else             { lo = 15; d = 1; wg = w4; bg = b4; }
            int a = o - lo;
            int base4 = o & ~3;
            for (int c = 0; c < d; c++)
                swf[o * 12 + (lo + c - base4 + 3)] = wg[a * d + c];
            sbf[o] = bg[a];
        }
    }
    __syncthreads();

    // Lane role: float4 index within its row (iteration stride 32 keeps it).
    const int k = threadIdx.x & 3;

    float W[40];
#pragma unroll
    for (int j = 0; j < 4; j++)
#pragma unroll
        for (int m = 0; m < 10; m++)
            W[j * 10 + m] = swf[(4 * k + j) * 12 + m];

    const float4* x4 = reinterpret_cast<const float4*>(x);
    float4* o4 = reinterpret_cast<float4*>(out);

    const int base = blockIdx.x * (TPB * ITERS) + threadIdx.x;
    const float4* xp = x4 + base;
    float4* op = o4 + base;

    const bool full = (blockIdx.x + 1) * (TPB * ITERS) <= n_f4;

    if (full) {
        // ---- fast path: no guards ----
        float4 v[ITERS];
#pragma unroll
        for (int t = 0; t < ITERS; t++)
            v[t] = __ldcs(xp + t * TPB);

#pragma unroll
        for (int t = 0; t < ITERS; t++) {
            float um3 = __shfl_up_sync(FULLMASK, v[t].y, 1);
            float um2 = __shfl_up_sync(FULLMASK, v[t].z, 1);
            float um1 = __shfl_up_sync(FULLMASK, v[t].w, 1);
            float dp4 = __shfl_down_sync(FULLMASK, v[t].x, 1);
            float dp5 = __shfl_down_sync(FULLMASK, v[t].y, 1);
            float dp6 = __shfl_down_sync(FULLMASK, v[t].z, 1);

            float r[4];
#pragma unroll
            for (int j = 0; j < 4; j++) {
                float acc = sbf[4 * k + j];
                acc = fmaf(W[j * 10 + 0], um3,     acc);
                acc = fmaf(W[j * 10 + 1], um2,     acc);
                acc = fmaf(W[j * 10 + 2], um1,     acc);
                acc = fmaf(W[j * 10 + 3], v[t].x,  acc);
                acc = fmaf(W[j * 10 + 4], v[t].y,  acc);
                acc = fmaf(W[j * 10 + 5], v[t].z,  acc);
                acc = fmaf(W[j * 10 + 6], v[t].w,  acc);
                acc = fmaf(W[j * 10 + 7], dp4,     acc);
                acc = fmaf(W[j * 10 + 8], dp5,     acc);
                acc = fmaf(W[j * 10 + 9], dp6,     acc);
                r[j] = acc;
            }
            __stcs(op + t * TPB, make_float4(r[0], r[1], r[2], r[3]));
        }
    } else {
        // ---- tail path: guarded (zero-fill keeps shuffles warp-uniform) ----
#pragma unroll
        for (int t = 0; t < ITERS; t++) {
            int idx = base + t * TPB;
            bool ok = idx < n_f4;
            float4 v = ok ? __ldcs(x4 + idx) : make_float4(0.f, 0.f, 0.f, 0.f);

            float um3 = __shfl_up_sync(FULLMASK, v.y, 1);
            float um2 = __shfl_up_sync(FULLMASK, v.z, 1);
            float um1 = __shfl_up_sync(FULLMASK, v.w, 1);
            float dp4 = __shfl_down_sync(FULLMASK, v.x, 1);
            float dp5 = __shfl_down_sync(FULLMASK, v.y, 1);
            float dp6 = __shfl_down_sync(FULLMASK, v.z, 1);

            float r[4];
#pragma unroll
            for (int j = 0; j < 4; j++) {
                float acc = sbf[4 * k + j];
                acc = fmaf(W[j * 10 + 0], um3, acc);
                acc = fmaf(W[j * 10 + 1], um2, acc);
                acc = fmaf(W[j * 10 + 2], um1, acc);
                acc = fmaf(W[j * 10 + 3], v.x, acc);
                acc = fmaf(W[j * 10 + 4], v.y, acc);
                acc = fmaf(W[j * 10 + 5], v.z, acc);
                acc = fmaf(W[j * 10 + 6], v.w, acc);
                acc = fmaf(W[j * 10 + 7], dp4, acc);
                acc = fmaf(W[j * 10 + 8], dp5, acc);
                acc = fmaf(W[j * 10 + 9], dp6, acc);
                r[j] = acc;
            }
            if (ok) __stcs(o4 + idx, make_float4(r[0], r[1], r[2], r[3]));
        }
    }
}

extern "C" void kernel_launch(void* const* d_in, const int* in_sizes, int n_in,
                              void* d_out, int out_size)
{
    const float* x  = (const float*)d_in[0];
    const float* w0 = (const float*)d_in[1];
    const float* b0 = (const float*)d_in[2];
    const float* w1 = (const float*)d_in[3];
    const float* b1 = (const float*)d_in[4];
    const float* w2 = (const float*)d_in[5];
    const float* b2 = (const float*)d_in[6];
    const float* w3 = (const float*)d_in[7];
    const float* b3 = (const float*)d_in[8];
    const float* w4 = (const float*)d_in[9];
    const float* b4 = (const float*)d_in[10];
    float* out = (float*)d_out;

    int n_f4 = in_sizes[0] / 4;
    int per_block = TPB * ITERS;
    int blocks = (n_f4 + per_block - 1) / per_block;

    gradewise_linear_kernel<<<blocks, TPB>>>(
        x, w0, b0, w1, b1, w2, b2, w3, b3, w4, b4, out, n_f4);
}

// round 10
// speedup vs baseline: 1.7417x; 1.0515x over previous
#include <cuda_runtime.h>
#include <cuda_bf16.h>

// GradeWiseLinear: block-diagonal 16x16 linear (blocks 1,4,6,4,1) + bias.
// 2,097,152 rows x 16 fp32. 268 MB HBM traffic, pure streaming.
//
// R10: 256-bit vectorized I/O (sm_100+ ld/st.global.v8.f32). Each lane owns
// HALF a row (8 consecutive floats, 32B aligned). Per 8 floats:
//   1 LDG.256 + 3 shuffles + 35 exact FMAs + 1 STG.256
// vs R9's 2 LDG.128 + 12 shuffles + 80 FMAs + 2 STG.128. Role = lane&1:
//   even half: outputs 0..7  = [scalar w0 | 4x4 W1 | rows 0-2 of 6x6 W2]
//   odd  half: outputs 8..15 = [rows 3-5 of W2 | 4x4 W3 | scalar w4]
// Cross-half inputs (3 floats each way) via one shfl_xor(1) round with
// role-based source select. All control flow warp-uniform.

#define TPB 256
#define ITERS 2
#define FULLMASK 0xffffffffu

// per-role smem weight table layout (48 floats per role):
//  [0..15]  Q  (4x4 block: W1 for role0, W3 for role1)
//  [16..19] QB (its bias)
//  [20..37] H  (3x6 half of W2: rows 0-2 role0, rows 3-5 role1)
//  [38..40] HB (its bias half)
//  [41]     ws (w0 / w4)   [42] bs (b0 / b4)

__global__ void __launch_bounds__(TPB, 3)
gradewise_linear_kernel(const float* __restrict__ x,
                        const float* __restrict__ w0, const float* __restrict__ b0,
                        const float* __restrict__ w1, const float* __restrict__ b1,
                        const float* __restrict__ w2, const float* __restrict__ b2,
                        const float* __restrict__ w3, const float* __restrict__ b3,
                        const float* __restrict__ w4, const float* __restrict__ b4,
                        float* __restrict__ out, int n_chunk)
{
    __shared__ __align__(16) float sW[2][48];
    if (threadIdx.x == 0) {
        sW[0][41] = w0[0];  sW[0][42] = b0[0];
        sW[1][41] = w4[0];  sW[1][42] = b4[0];
#pragma unroll
        for (int i = 0; i < 16; i++) { sW[0][i] = w1[i]; sW[1][i] = w3[i]; }
#pragma unroll
        for (int j = 0; j < 4; j++)  { sW[0][16 + j] = b1[j]; sW[1][16 + j] = b3[j]; }
#pragma unroll
        for (int j = 0; j < 3; j++) {
#pragma unroll
            for (int i = 0; i < 6; i++) {
                sW[0][20 + j * 6 + i] = w2[j * 6 + i];
                sW[1][20 + j * 6 + i] = w2[(3 + j) * 6 + i];
            }
            sW[0][38 + j] = b2[j];
            sW[1][38 + j] = b2[3 + j];
        }
    }
    __syncthreads();

    const int role = threadIdx.x & 1;          // 0: first half-row, 1: second
    const float* T = sW[role];

    float Q[16], QB[4], H[18], HB[3];
#pragma unroll
    for (int i = 0; i < 16; i++) Q[i] = T[i];
#pragma unroll
    for (int j = 0; j < 4; j++)  QB[j] = T[16 + j];
#pragma unroll
    for (int i = 0; i < 18; i++) H[i] = T[20 + i];
#pragma unroll
    for (int j = 0; j < 3; j++)  HB[j] = T[38 + j];
    const float ws = T[41], bs = T[42];

    const int base = blockIdx.x * (TPB * ITERS) + threadIdx.x;
    const bool full = (blockIdx.x + 1) * (TPB * ITERS) <= n_chunk;

    float a[ITERS][8];
    bool ok[ITERS];

    // ---- phase 1: issue all 256-bit loads (independent) ----
#pragma unroll
    for (int t = 0; t < ITERS; t++) {
        int idx = base + t * TPB;
        ok[t] = full || (idx < n_chunk);
        const float* p = x + (size_t)idx * 8;
        if (ok[t]) {
            asm volatile(
                "ld.global.v8.f32 {%0,%1,%2,%3,%4,%5,%6,%7}, [%8];"
                : "=f"(a[t][0]), "=f"(a[t][1]), "=f"(a[t][2]), "=f"(a[t][3]),
                  "=f"(a[t][4]), "=f"(a[t][5]), "=f"(a[t][6]), "=f"(a[t][7])
                : "l"(p));
        } else {
#pragma unroll
            for (int i = 0; i < 8; i++) a[t][i] = 0.0f;
        }
    }

    // ---- phase 2: exchange + compute + store ----
#pragma unroll
    for (int t = 0; t < ITERS; t++) {
        // Partner exchange: even lane needs odd's a0..a2 (x8..x10);
        // odd lane needs even's a5..a7 (x5..x7). Contribute what partner needs.
        float s0 = role ? a[t][0] : a[t][5];
        float s1 = role ? a[t][1] : a[t][6];
        float s2 = role ? a[t][2] : a[t][7];
        float p0 = __shfl_xor_sync(FULLMASK, s0, 1);
        float p1 = __shfl_xor_sync(FULLMASK, s1, 1);
        float p2 = __shfl_xor_sync(FULLMASK, s2, 1);

        // scalar block
        float vsc = role ? a[t][7] : a[t][0];
        float sc = fmaf(ws, vsc, bs);

        // quad block inputs: role0 -> x1..x4 = a1..a4; role1 -> x11..x14 = a3..a6
        float q0 = role ? a[t][3] : a[t][1];
        float q1 = role ? a[t][4] : a[t][2];
        float q2 = role ? a[t][5] : a[t][3];
        float q3 = role ? a[t][6] : a[t][4];
        float qo[4];
#pragma unroll
        for (int j = 0; j < 4; j++) {
            float acc = QB[j];
            acc = fmaf(Q[j * 4 + 0], q0, acc);
            acc = fmaf(Q[j * 4 + 1], q1, acc);
            acc = fmaf(Q[j * 4 + 2], q2, acc);
            acc = fmaf(Q[j * 4 + 3], q3, acc);
            qo[j] = acc;
        }

        // hex block inputs x5..x10:
        // role0: a5,a6,a7,p0,p1,p2   role1: p0,p1,p2,a0,a1,a2
        float h0 = role ? p0 : a[t][5];
        float h1 = role ? p1 : a[t][6];
        float h2 = role ? p2 : a[t][7];
        float h3 = role ? a[t][0] : p0;
        float h4 = role ? a[t][1] : p1;
        float h5 = role ? a[t][2] : p2;
        float ho[3];
#pragma unroll
        for (int j = 0; j < 3; j++) {
            float acc = HB[j];
            acc = fmaf(H[j * 6 + 0], h0, acc);
            acc = fmaf(H[j * 6 + 1], h1, acc);
            acc = fmaf(H[j * 6 + 2], h2, acc);
            acc = fmaf(H[j * 6 + 3], h3, acc);
            acc = fmaf(H[j * 6 + 4], h4, acc);
            acc = fmaf(H[j * 6 + 5], h5, acc);
            ho[j] = acc;
        }

        // output arrangement:
        // role0: {sc, qo0..3, ho0..2}   role1: {ho0..2, qo0..3, sc}
        float o0 = role ? ho[0] : sc;
        float o1 = role ? ho[1] : qo[0];
        float o2 = role ? ho[2] : qo[1];
        float o3 = role ? qo[0] : qo[2];
        float o4 = role ? qo[1] : qo[3];
        float o5 = role ? qo[2] : ho[0];
        float o6 = role ? qo[3] : ho[1];
        float o7 = role ? sc    : ho[2];

        if (ok[t]) {
            int idx = base + t * TPB;
            float* p = out + (size_t)idx * 8;
            asm volatile(
                "st.global.v8.f32 [%0], {%1,%2,%3,%4,%5,%6,%7,%8};"
                :: "l"(p),
                   "f"(o0), "f"(o1), "f"(o2), "f"(o3),
                   "f"(o4), "f"(o5), "f"(o6), "f"(o7)
                : "memory");
        }
    }
}

extern "C" void kernel_launch(void* const* d_in, const int* in_sizes, int n_in,
                              void* d_out, int out_size)
{
    const float* x  = (const float*)d_in[0];
    const float* w0 = (const float*)d_in[1];
    const float* b0 = (const float*)d_in[2];
    const float* w1 = (const float*)d_in[3];
    const float* b1 = (const float*)d_in[4];
    const float* w2 = (const float*)d_in[5];
    const float* b2 = (const float*)d_in[6];
    const float* w3 = (const float*)d_in[7];
    const float* b3 = (const float*)d_in[8];
    const float* w4 = (const float*)d_in[9];
    const float* b4 = (const float*)d_in[10];
    float* out = (float*)d_out;

    int n_chunk = in_sizes[0] / 8;          // 8-float half-rows
    int per_block = TPB * ITERS;
    int blocks = (n_chunk + per_block - 1) / per_block;

    gradewise_linear_kernel<<<blocks, TPB>>>(
        x, w0, b0, w1, b1, w2, b2, w3, b3, w4, b4, out, n_chunk);
}

// round 11
// speedup vs baseline: 1.8890x; 1.0846x over previous
#include <cuda_runtime.h>
#include <cuda_bf16.h>

// GradeWiseLinear: block-diagonal 16x16 linear (blocks 1,4,6,4,1) + bias.
// 2,097,152 rows x 16 fp32. 268 MB HBM traffic, pure streaming.
//
// R11: R10 (256-bit ld/st.global.v8.f32, half-row per lane, role = lane&1,
// one shfl_xor exchange round, exact per-role block compute) with ITERS=3:
// three independent LDG.256 issued before any compute -> ~10.9 MB in
// flight chip-wide (+50% vs R10), pushing the DRAM concurrency ceiling.

#define TPB 256
#define ITERS 3
#define FULLMASK 0xffffffffu

// per-role smem weight table (48 floats per role):
//  [0..15]  Q  (4x4: W1 role0 / W3 role1)   [16..19] QB
//  [20..37] H  (3x6 half of W2)             [38..40] HB
//  [41] ws (w0/w4)   [42] bs (b0/b4)

__global__ void __launch_bounds__(TPB, 3)
gradewise_linear_kernel(const float* __restrict__ x,
                        const float* __restrict__ w0, const float* __restrict__ b0,
                        const float* __restrict__ w1, const float* __restrict__ b1,
                        const float* __restrict__ w2, const float* __restrict__ b2,
                        const float* __restrict__ w3, const float* __restrict__ b3,
                        const float* __restrict__ w4, const float* __restrict__ b4,
                        float* __restrict__ out, int n_chunk)
{
    __shared__ __align__(16) float sW[2][48];
    if (threadIdx.x == 0) {
        sW[0][41] = w0[0];  sW[0][42] = b0[0];
        sW[1][41] = w4[0];  sW[1][42] = b4[0];
#pragma unroll
        for (int i = 0; i < 16; i++) { sW[0][i] = w1[i]; sW[1][i] = w3[i]; }
#pragma unroll
        for (int j = 0; j < 4; j++)  { sW[0][16 + j] = b1[j]; sW[1][16 + j] = b3[j]; }
#pragma unroll
        for (int j = 0; j < 3; j++) {
#pragma unroll
            for (int i = 0; i < 6; i++) {
                sW[0][20 + j * 6 + i] = w2[j * 6 + i];
                sW[1][20 + j * 6 + i] = w2[(3 + j) * 6 + i];
            }
            sW[0][38 + j] = b2[j];
            sW[1][38 + j] = b2[3 + j];
        }
    }
    __syncthreads();

    const int role = threadIdx.x & 1;
    const float* T = sW[role];

    float Q[16], QB[4], H[18], HB[3];
#pragma unroll
    for (int i = 0; i < 16; i++) Q[i] = T[i];
#pragma unroll
    for (int j = 0; j < 4; j++)  QB[j] = T[16 + j];
#pragma unroll
    for (int i = 0; i < 18; i++) H[i] = T[20 + i];
#pragma unroll
    for (int j = 0; j < 3; j++)  HB[j] = T[38 + j];
    const float ws = T[41], bs = T[42];

    const int base = blockIdx.x * (TPB * ITERS) + threadIdx.x;
    const bool full = (blockIdx.x + 1) * (TPB * ITERS) <= n_chunk;

    float a[ITERS][8];
    bool ok[ITERS];

    // ---- phase 1: issue all 256-bit loads (independent, MLP=ITERS) ----
#pragma unroll
    for (int t = 0; t < ITERS; t++) {
        int idx = base + t * TPB;
        ok[t] = full || (idx < n_chunk);
        const float* p = x + (size_t)idx * 8;
        if (ok[t]) {
            asm volatile(
                "ld.global.v8.f32 {%0,%1,%2,%3,%4,%5,%6,%7}, [%8];"
                : "=f"(a[t][0]), "=f"(a[t][1]), "=f"(a[t][2]), "=f"(a[t][3]),
                  "=f"(a[t][4]), "=f"(a[t][5]), "=f"(a[t][6]), "=f"(a[t][7])
                : "l"(p));
        } else {
#pragma unroll
            for (int i = 0; i < 8; i++) a[t][i] = 0.0f;
        }
    }

    // ---- phase 2: exchange + compute + store per sub-iteration ----
#pragma unroll
    for (int t = 0; t < ITERS; t++) {
        // even lane needs odd's a0..a2 (x8..x10); odd needs even's a5..a7.
        float s0 = role ? a[t][0] : a[t][5];
        float s1 = role ? a[t][1] : a[t][6];
        float s2 = role ? a[t][2] : a[t][7];
        float p0 = __shfl_xor_sync(FULLMASK, s0, 1);
        float p1 = __shfl_xor_sync(FULLMASK, s1, 1);
        float p2 = __shfl_xor_sync(FULLMASK, s2, 1);

        // scalar block
        float vsc = role ? a[t][7] : a[t][0];
        float sc = fmaf(ws, vsc, bs);

        // quad block inputs: role0 x1..x4 = a1..a4; role1 x11..x14 = a3..a6
        float q0 = role ? a[t][3] : a[t][1];
        float q1 = role ? a[t][4] : a[t][2];
        float q2 = role ? a[t][5] : a[t][3];
        float q3 = role ? a[t][6] : a[t][4];
        float qo[4];
#pragma unroll
        for (int j = 0; j < 4; j++) {
            float acc = QB[j];
            acc = fmaf(Q[j * 4 + 0], q0, acc);
            acc = fmaf(Q[j * 4 + 1], q1, acc);
            acc = fmaf(Q[j * 4 + 2], q2, acc);
            acc = fmaf(Q[j * 4 + 3], q3, acc);
            qo[j] = acc;
        }

        // hex block inputs x5..x10:
        // role0: a5,a6,a7,p0,p1,p2   role1: p0,p1,p2,a0,a1,a2
        float h0 = role ? p0 : a[t][5];
        float h1 = role ? p1 : a[t][6];
        float h2 = role ? p2 : a[t][7];
        float h3 = role ? a[t][0] : p0;
        float h4 = role ? a[t][1] : p1;
        float h5 = role ? a[t][2] : p2;
        float ho[3];
#pragma unroll
        for (int j = 0; j < 3; j++) {
            float acc = HB[j];
            acc = fmaf(H[j * 6 + 0], h0, acc);
            acc = fmaf(H[j * 6 + 1], h1, acc);
            acc = fmaf(H[j * 6 + 2], h2, acc);
            acc = fmaf(H[j * 6 + 3], h3, acc);
            acc = fmaf(H[j * 6 + 4], h4, acc);
            acc = fmaf(H[j * 6 + 5], h5, acc);
            ho[j] = acc;
        }

        // output order: role0 {sc,qo0..3,ho0..2}; role1 {ho0..2,qo0..3,sc}
        float o0 = role ? ho[0] : sc;
        float o1 = role ? ho[1] : qo[0];
        float o2 = role ? ho[2] : qo[1];
        float o3 = role ? qo[0] : qo[2];
        float o4 = role ? qo[1] : qo[3];
        float o5 = role ? qo[2] : ho[0];
        float o6 = role ? qo[3] : ho[1];
        float o7 = role ? sc    : ho[2];

        if (ok[t]) {
            int idx = base + t * TPB;
            float* p = out + (size_t)idx * 8;
            asm volatile(
                "st.global.v8.f32 [%0], {%1,%2,%3,%4,%5,%6,%7,%8};"
                :: "l"(p),
                   "f"(o0), "f"(o1), "f"(o2), "f"(o3),
                   "f"(o4), "f"(o5), "f"(o6), "f"(o7)
                : "memory");
        }
    }
}

extern "C" void kernel_launch(void* const* d_in, const int* in_sizes, int n_in,
                              void* d_out, int out_size)
{
    const float* x  = (const float*)d_in[0];
    const float* w0 = (const float*)d_in[1];
    const float* b0 = (const float*)d_in[2];
    const float* w1 = (const float*)d_in[3];
    const float* b1 = (const float*)d_in[4];
    const float* w2 = (const float*)d_in[5];
    const float* b2 = (const float*)d_in[6];
    const float* w3 = (const float*)d_in[7];
    const float* b3 = (const float*)d_in[8];
    const float* w4 = (const float*)d_in[9];
    const float* b4 = (const float*)d_in[10];
    float* out = (float*)d_out;

    int n_chunk = in_sizes[0] / 8;          // 8-float half-rows
    int per_block = TPB * ITERS;
    int blocks = (n_chunk + per_block - 1) / per_block;

    gradewise_linear_kernel<<<blocks, TPB>>>(
        x, w0, b0, w1, b1, w2, b2, w3, b3, w4, b4, out, n_chunk);
}